// round 15
// baseline (speedup 1.0000x reference)
#include <cuda_runtime.h>
#include <math.h>

// Problem constants
#define B    8
#define S    2048
#define D    1024
#define NB   20
#define NROW (B * NB)        // 160
#define NCTA 128
#define NKS  16              // k-slices
#define KSL  64              // k per slice
#define CPC  128             // cols per CTA
#define EPS  1e-8f

typedef unsigned long long ull;

// ---------------- static device scratch ----------------
__device__ float g_x   [B * S * D];
__device__ float g_wx  [B * S * D];
__device__ float g_kx  [B * S * NB];
__device__ float g_Ut  [D * D];
__device__ float g_Vt  [D * D];
__device__ float g_KV  [NB * D];
__device__ float g_h   [NROW * D];
__device__ float g_hdup[NROW * 2 * D];       // {h,h} pairs, 1.25 MB
__device__ float g_part[NKS * NROW * D];     // k-slice partials, 10 MB

__device__ unsigned g_bar_count = 0;
__device__ volatile unsigned g_bar_gen = 0;

// ---------------- f32x2 helpers ----------------
__device__ __forceinline__ void fma2(ull& a, ull x, ull y) {
    asm("fma.rn.f32x2 %0, %1, %2, %0;" : "+l"(a) : "l"(x), "l"(y));
}
__device__ __forceinline__ float2 ull2f2(ull v) {
    float2 r;
    asm("mov.b64 {%0, %1}, %2;" : "=f"(r.x), "=f"(r.y) : "l"(v));
    return r;
}

__device__ __forceinline__ float ftanh(float v) {
    float e = __expf(2.f * v);
    return 1.f - __fdividef(2.f, e + 1.f);
}
__device__ __forceinline__ float fsigm(float v) {
    return __fdividef(1.f, 1.f + __expf(-v));
}

// ---------------- grid barrier (persistent kernel) ----------------
__device__ __forceinline__ void grid_barrier() {
    __threadfence();
    __syncthreads();
    if (threadIdx.x == 0) {
        unsigned g = g_bar_gen;
        if (atomicAdd(&g_bar_count, 1u) == NCTA - 1) {
            atomicExch(&g_bar_count, 0u);
            __threadfence();
            g_bar_gen = g + 1u;
        } else {
            while (g_bar_gen == g) { }
        }
    }
    __syncthreads();
}

// ---------------- precompute kernels ----------------
__global__ __launch_bounds__(256) void k_init_h(const float* __restrict__ state) {
    int s = blockIdx.x, b = blockIdx.y;
    int tid = threadIdx.x;
    int row = b * NB + s;
    float4 v = ((const float4*)(state + s * D))[tid];
    ((float4*)(g_h + row * D))[tid] = v;
    float4 d0 = make_float4(v.x, v.x, v.y, v.y);
    float4 d1 = make_float4(v.z, v.z, v.w, v.w);
    float* dp = g_hdup + row * 2 * D + tid * 8;
    *(float4*)(dp)     = d0;
    *(float4*)(dp + 4) = d1;
}

__global__ __launch_bounds__(256) void k_prep_x(const float* __restrict__ e,
                                                const float* __restrict__ m,
                                                const float* __restrict__ keys) {
    int t = blockIdx.x, b = blockIdx.y;
    int tid = threadIdx.x;
    __shared__ float xs[D];
    int base = (b * S + t) * D;
    float4 ev = ((const float4*)(e + base))[tid];
    float4 mv = ((const float4*)(m + base))[tid];
    float4 xv;
    xv.x = ev.x + mv.x; xv.y = ev.y + mv.y;
    xv.z = ev.z + mv.z; xv.w = ev.w + mv.w;
    ((float4*)(g_x + base))[tid] = xv;
    ((float4*)xs)[tid] = xv;
    __syncthreads();
    int w = tid >> 5, l = tid & 31;
    for (int s2 = w; s2 < NB; s2 += 8) {
        const float* kr = keys + s2 * D;
        float a = 0.f;
        for (int i = l; i < D; i += 32) a += kr[i] * xs[i];
        #pragma unroll
        for (int o = 16; o; o >>= 1) a += __shfl_down_sync(0xffffffffu, a, o);
        if (l == 0) g_kx[(b * S + t) * NB + s2] = a;
    }
}

__global__ void k_transpose(const float* __restrict__ U, const float* __restrict__ V) {
    __shared__ float tile[32][33];
    const float* src = blockIdx.z ? V : U;
    float* dst = blockIdx.z ? g_Vt : g_Ut;
    int x0 = blockIdx.x * 32, y0 = blockIdx.y * 32;
    int tx = threadIdx.x, ty = threadIdx.y;
    #pragma unroll
    for (int i = 0; i < 32; i += 8)
        tile[ty + i][tx] = src[(y0 + ty + i) * D + x0 + tx];
    __syncthreads();
    #pragma unroll
    for (int i = 0; i < 32; i += 8)
        dst[(x0 + ty + i) * D + y0 + tx] = tile[tx][ty + i];
}

__global__ __launch_bounds__(128) void k_kv(const float* __restrict__ keys) {
    int s = blockIdx.y;
    int d = blockIdx.x * 128 + threadIdx.x;
    float acc = 0.f;
    const float* kr = keys + s * D;
    #pragma unroll 8
    for (int k = 0; k < D; k++) acc += kr[k] * g_Vt[k * D + d];
    g_KV[s * D + d] = acc;
}

// g_wx[row][d] = sum_k g_x[row][k] * W[d][k]
#define BM 64
#define BN 64
#define BK 32
#define PAD 4
__global__ __launch_bounds__(256) void k_wx_gemm(const float* __restrict__ W) {
    int n0 = blockIdx.x * BN;
    int m0 = blockIdx.y * BM;
    __shared__ float Xs[BK][BM + PAD];
    __shared__ float Ws[BK][BN + PAD];
    int tid = threadIdx.x;
    int tx = tid & 15, ty = tid >> 4;
    float acc[4][4];
    #pragma unroll
    for (int r = 0; r < 4; r++)
        #pragma unroll
        for (int c = 0; c < 4; c++) acc[r][c] = 0.f;

    for (int k0 = 0; k0 < D; k0 += BK) {
        #pragma unroll
        for (int i = 0; i < 2; i++) {
            int f = tid + i * 256;
            int r = f >> 3, kq = (f & 7) * 4;
            float4 xv = *(const float4*)(g_x + (m0 + r) * D + k0 + kq);
            Xs[kq + 0][r] = xv.x; Xs[kq + 1][r] = xv.y;
            Xs[kq + 2][r] = xv.z; Xs[kq + 3][r] = xv.w;
            float4 wv = *(const float4*)(W + (n0 + r) * D + k0 + kq);
            Ws[kq + 0][r] = wv.x; Ws[kq + 1][r] = wv.y;
            Ws[kq + 2][r] = wv.z; Ws[kq + 3][r] = wv.w;
        }
        __syncthreads();
        #pragma unroll
        for (int k = 0; k < BK; k++) {
            float4 a  = *(const float4*)&Xs[k][ty * 4];
            float4 bq = *(const float4*)&Ws[k][tx * 4];
            float ar[4] = {a.x, a.y, a.z, a.w};
            float br[4] = {bq.x, bq.y, bq.z, bq.w};
            #pragma unroll
            for (int r = 0; r < 4; r++)
                #pragma unroll
                for (int c = 0; c < 4; c++)
                    acc[r][c] = fmaf(ar[r], br[c], acc[r][c]);
        }
        __syncthreads();
    }
    #pragma unroll
    for (int r = 0; r < 4; r++) {
        float4 o = {acc[r][0], acc[r][1], acc[r][2], acc[r][3]};
        *(float4*)(g_wx + (m0 + ty * 4 + r) * D + n0 + tx * 4) = o;
    }
}

// ---------------- persistent scan kernel ----------------
// 128 CTAs x 256 threads, 1 CTA/SM (co-resident).
// Phase1: CTA(cg 0..7, ks 0..15) owns U tile [64 k x 128 cols] in SMEM
//         (loaded once). Warp = 20 rows, lane = 4 cols. Writes k-slice
//         partials to g_part.
// Phase2: CTAs 0..79 each update 2 rows (half-block per row): gate, tanh,
//         normalize; writes g_h + g_hdup (+ out at t==S-1).
__global__ __launch_bounds__(256, 1) void k_scan(float* __restrict__ out) {
    const int tid = threadIdx.x;
    const int w = tid >> 5, l = tid & 31;
    const int cta = blockIdx.x;
    const int cg = cta & 7;
    const int ks = cta >> 3;
    const int c0 = cg * CPC;
    const int k0 = ks * KSL;
    const int r0 = w * 20;

    __shared__ float u_s[KSL * CPC];        // 32 KB
    __shared__ float s_r[2][4];
    __shared__ float s_g[2];
    __shared__ float s_i[2];

    // load U tile once (persists across all 2048 steps)
    for (int i = tid; i < KSL * (CPC / 4); i += 256) {
        int kr = i >> 5, cq = (i & 31) * 4;
        *(float4*)&u_s[kr * CPC + cq] =
            *(const float4*)(g_Ut + (k0 + kr) * D + c0 + cq);
    }
    __syncthreads();

    const float* us_l = u_s + l * 4;
    const float* hd0  = g_hdup + r0 * (2 * D) + k0 * 2;
    float* pp = g_part + (ks * NROW + r0) * D + c0 + l * 4;

    // phase2 role
    const int half = tid >> 7;
    const int gi   = tid & 127;
    const int row2 = cta * 2 + half;           // valid when cta < 80
    const int b2   = row2 / NB;
    const int sl2  = row2 - b2 * NB;
    const int wq   = (tid >> 5) & 3;
    const int c1 = gi * 4, c2 = 512 + gi * 4;

    for (int t = 0; t < S; t++) {
        // ===== phase 1: partial[row][c] = sum_{k in slice} h[row][k]*Ut[k][c]
        ull acc0[20], acc1[20];
        #pragma unroll
        for (int j = 0; j < 20; j++) { acc0[j] = 0ull; acc1[j] = 0ull; }

        #pragma unroll 1
        for (int kk = 0; kk < KSL; kk += 2) {
            ulonglong2 uA = *(const ulonglong2*)(us_l + kk * CPC);
            ulonglong2 uB = *(const ulonglong2*)(us_l + (kk + 1) * CPC);
            const float* hdk = hd0 + kk * 2;
            #pragma unroll
            for (int j = 0; j < 20; j++) {
                ulonglong2 hh = *(const ulonglong2*)(hdk + j * (2 * D));
                fma2(acc0[j], hh.x, uA.x);
                fma2(acc1[j], hh.x, uA.y);
                fma2(acc0[j], hh.y, uB.x);
                fma2(acc1[j], hh.y, uB.y);
            }
        }

        #pragma unroll
        for (int j = 0; j < 20; j++) {
            float2 a = ull2f2(acc0[j]);
            float2 bq = ull2f2(acc1[j]);
            *(float4*)(pp + j * D) = make_float4(a.x, a.y, bq.x, bq.y);
        }

        grid_barrier();

        // ===== phase 2: rows 2*cta, 2*cta+1 on half-blocks =====
        if (cta < 80) {
            float* hrow = g_h + row2 * D;
            const float* xrow = g_x + (b2 * S + t) * D;
            float4 h1 = *(const float4*)(hrow + c1);
            float4 h2 = *(const float4*)(hrow + c2);
            float4 x1 = *(const float4*)(xrow + c1);
            float4 x2 = *(const float4*)(xrow + c2);

            // sum the 16 k-slice partials (+ KV + Wx) while the gate reduces
            float4 p1 = *(const float4*)(g_KV + sl2 * D + c1);
            float4 p2 = *(const float4*)(g_KV + sl2 * D + c2);
            {
                const float* wxr = g_wx + (b2 * S + t) * D;
                float4 a = *(const float4*)(wxr + c1);
                float4 bq = *(const float4*)(wxr + c2);
                p1.x += a.x; p1.y += a.y; p1.z += a.z; p1.w += a.w;
                p2.x += bq.x; p2.y += bq.y; p2.z += bq.z; p2.w += bq.w;
            }
            #pragma unroll
            for (int q = 0; q < NKS; q++) {
                const float* pr = g_part + (q * NROW + row2) * D;
                float4 a = *(const float4*)(pr + c1);
                float4 bq = *(const float4*)(pr + c2);
                p1.x += a.x; p1.y += a.y; p1.z += a.z; p1.w += a.w;
                p2.x += bq.x; p2.y += bq.y; p2.z += bq.z; p2.w += bq.w;
            }

            float p = h1.x * x1.x + h1.y * x1.y + h1.z * x1.z + h1.w * x1.w
                    + h2.x * x2.x + h2.y * x2.y + h2.z * x2.z + h2.w * x2.w;
            #pragma unroll
            for (int o = 16; o; o >>= 1) p += __shfl_down_sync(0xffffffffu, p, o);
            if ((gi & 31) == 0) s_r[half][wq] = p;
            __syncthreads();
            if (gi == 0) {
                float v = s_r[half][0] + s_r[half][1] + s_r[half][2] + s_r[half][3];
                v += g_kx[(b2 * S + t) * NB + sl2];
                s_g[half] = fsigm(v);
            }
            __syncthreads();
            float gg = s_g[half];

            float4 hn1, hn2;
            hn1.x = h1.x + gg * ftanh(p1.x);
            hn1.y = h1.y + gg * ftanh(p1.y);
            hn1.z = h1.z + gg * ftanh(p1.z);
            hn1.w = h1.w + gg * ftanh(p1.w);
            hn2.x = h2.x + gg * ftanh(p2.x);
            hn2.y = h2.y + gg * ftanh(p2.y);
            hn2.z = h2.z + gg * ftanh(p2.z);
            hn2.w = h2.w + gg * ftanh(p2.w);

            float q2 = hn1.x * hn1.x + hn1.y * hn1.y + hn1.z * hn1.z + hn1.w * hn1.w
                     + hn2.x * hn2.x + hn2.y * hn2.y + hn2.z * hn2.z + hn2.w * hn2.w;
            #pragma unroll
            for (int o = 16; o; o >>= 1) q2 += __shfl_down_sync(0xffffffffu, q2, o);
            if ((gi & 31) == 0) s_r[half][wq] = q2;
            __syncthreads();
            if (gi == 0) {
                float v = s_r[half][0] + s_r[half][1] + s_r[half][2] + s_r[half][3];
                s_i[half] = __fdividef(1.f, sqrtf(v) + EPS);
            }
            __syncthreads();
            float inv = s_i[half];
            hn1.x *= inv; hn1.y *= inv; hn1.z *= inv; hn1.w *= inv;
            hn2.x *= inv; hn2.y *= inv; hn2.z *= inv; hn2.w *= inv;

            *(float4*)(hrow + c1) = hn1;
            *(float4*)(hrow + c2) = hn2;
            float* dp1 = g_hdup + row2 * (2 * D) + c1 * 2;
            float* dp2 = g_hdup + row2 * (2 * D) + c2 * 2;
            *(float4*)(dp1)     = make_float4(hn1.x, hn1.x, hn1.y, hn1.y);
            *(float4*)(dp1 + 4) = make_float4(hn1.z, hn1.z, hn1.w, hn1.w);
            *(float4*)(dp2)     = make_float4(hn2.x, hn2.x, hn2.y, hn2.y);
            *(float4*)(dp2 + 4) = make_float4(hn2.z, hn2.z, hn2.w, hn2.w);

            if (t == S - 1) {
                *(float4*)(out + row2 * D + c1) = hn1;
                *(float4*)(out + row2 * D + c2) = hn2;
            }
        }

        grid_barrier();
    }
}

// ---------------- launch ----------------
extern "C" void kernel_launch(void* const* d_in, const int* in_sizes, int n_in,
                              void* d_out, int out_size) {
    const float* e     = (const float*)d_in[0];
    const float* m     = (const float*)d_in[1];
    const float* state = (const float*)d_in[2];
    const float* U     = (const float*)d_in[3];
    const float* V     = (const float*)d_in[4];
    const float* W     = (const float*)d_in[5];
    const float* keys  = (const float*)d_in[6];
    float* out = (float*)d_out;

    k_init_h   <<<dim3(NB, B), 256>>>(state);
    k_prep_x   <<<dim3(S, B), 256>>>(e, m, keys);
    k_transpose<<<dim3(32, 32, 2), dim3(32, 8)>>>(U, V);
    k_kv       <<<dim3(D / 128, NB), 128>>>(keys);
    k_wx_gemm  <<<dim3(D / BN, (B * S) / BM), 256>>>(W);
    k_scan     <<<NCTA, 256>>>(out);
}